// round 15
// baseline (speedup 1.0000x reference)
#include <cuda_runtime.h>
#include <cuda_bf16.h>
#include <cuda_fp16.h>

// ThermoQuantizer: groupwise abs-mean scale + softmax quantization onto a
// uniform 16-level codebook + lerp.
//
// Core (R13/R14 winners): per-block 2048-entry fp16x2 linear-interp LUT of
// qxn(xn) over [-12,12] built via exact palindromic-Horner; LDS.32 lookups;
// default-policy loads (x lives in L2 across graph replays); .cs stores;
// depth-1 register prefetch; persistent single wave 152x5 blocks.
//
// Round-15: instruction-diet. Measured ~225 warp-instrs/tile vs ~80 essential.
//   - pointer-increment addressing (fixed byte stride/iter, no IMAD.WIDE chains)
//   - guard-free main loop over FULL tiles only (partial tile, if any, in a
//     separate guarded epilogue block; compute stays whole-warp for shfl)
//   - scalar epilogue res = fma(pm, qv, onemp*x) (no f32x2 pack/unpack MOVs)
//   - contiguous 8-float-per-thread mapping (half-warp = one 128-elem group)

typedef unsigned long long ull;
#define FULL_MASK 0xFFFFFFFFu

#define TAB_N    2048
#define TAB_XMIN -12.0f
#define TAB_INVH (2048.0f / 24.0f)
#define TAB_OFF  1024.0f
#define TAB_UMAX 2047.999f

__device__ const float gTcol[56] = {
    0.f,-2.f, 0.f,  2.f, 0.f,-2.f, 0.f,   // j=0
    1.f, 0.f,-3.f,  0.f, 5.f, 0.f,-7.f,   // j=1
    0.f, 1.f, 0.f, -4.f, 0.f, 9.f, 0.f,   // j=2
    0.f, 0.f, 1.f,  0.f,-5.f, 0.f,14.f,   // j=3
    0.f, 0.f, 0.f,  1.f, 0.f,-6.f, 0.f,   // j=4
    0.f, 0.f, 0.f,  0.f, 1.f, 0.f,-7.f,   // j=5
    0.f, 0.f, 0.f,  0.f, 0.f, 1.f, 0.f,   // j=6
    0.f, 0.f, 0.f,  0.f, 0.f, 0.f, 1.f};  // j=7

__device__ __forceinline__ ull pk2(float lo, float hi) {
    ull r; asm("mov.b64 %0, {%1, %2};" : "=l"(r) : "f"(lo), "f"(hi)); return r;
}
__device__ __forceinline__ float ex2f(float a) {
    float r; asm("ex2.approx.ftz.f32 %0, %1;" : "=f"(r) : "f"(a)); return r;
}
__device__ __forceinline__ float rcpf(float a) {
    float r; asm("rcp.approx.ftz.f32 %0, %1;" : "=f"(r) : "f"(a)); return r;
}
__device__ __forceinline__ void stcs4(float4* p, float4 v) {
    asm volatile("st.global.cs.v4.f32 [%0], {%1,%2,%3,%4};"
                 :: "l"(p), "f"(v.x), "f"(v.y), "f"(v.z), "f"(v.w) : "memory");
}

__global__ __launch_bounds__(256, 5) void ThermoQuantizer_50122268345057_kernel(
    const float* __restrict__ x,
    const float* __restrict__ cb,
    const float* __restrict__ pp,
    const float* __restrict__ pt,
    float* __restrict__ out,
    int n4)
{
    __shared__ __half2 sTabH[TAB_N];     // packed fp16 (f_i, f_{i+1}-f_i)
    __shared__ float sF[TAB_N + 1];      // node values (build scratch, fp32)
    __shared__ ull   sC[16];             // (q_j,q_j) j=0..7 then (s_j,s_j)
    __shared__ float sK2, sPres;

    const int tid = threadIdx.x;

    // ---- stage 1: Q,S coefficient derivation (warp 0, lane-parallel) ----
    if (tid < 32) {
        const int lane0 = tid;
        const int k = lane0 & 15;
        const float invT = 1.0f / (pt[0] + 1e-6f);
        const float c = cb[k];
        const float g = __expf(-c * c * invT);
        const float Hk = g * c;

        float sg = (k & 1) ? -g : g;     // p: alternating prefix sum
        float sh = Hk;                   // m: plain prefix sum (negated)
        #pragma unroll
        for (int o = 1; o <= 8; o <<= 1) {
            float tg = __shfl_up_sync(FULL_MASK, sg, o);
            float th = __shfl_up_sync(FULL_MASK, sh, o);
            if (lane0 >= o) { sg += tg; sh += th; }
        }
        const float pv = (k & 1) ? -sg : sg;
        const float mv = -sh;

        float pb[8], mb[8];
        #pragma unroll
        for (int t = 0; t < 8; ++t) {
            pb[t] = __shfl_sync(FULL_MASK, pv, 7 + t);
            mb[t] = __shfl_sync(FULL_MASK, mv, 7 + t);
        }
        if (lane0 < 8) {
            float q = (lane0 == 0) ? pb[0] : 0.f;
            float s = (lane0 == 0) ? mb[0] : 0.f;
            const float* Tc = &gTcol[lane0 * 7];
            #pragma unroll
            for (int t = 1; t <= 7; ++t) {
                float tc = Tc[t - 1];
                q = fmaf(pb[t], tc, q);
                s = fmaf(mb[t], tc, s);
            }
            sC[lane0]     = pk2(q, q);
            sC[lane0 + 8] = pk2(s, s);
        }
        if (lane0 == 0) {
            sK2 = 2.0f * (cb[1] - cb[0]) * invT * 1.4426950408889634f;
            sPres = pp[0];
        }
    }
    __syncthreads();

    // ---- stage 2: build qxn table (all 256 threads), pack to fp16x2 ----
    {
        const float* sCf = reinterpret_cast<const float*>(sC);
        const float K2 = sK2;
        for (int i = tid; i <= TAB_N; i += 256) {
            float xn = TAB_XMIN + (float)i * (1.0f / TAB_INVH);
            float a = fminf(fmaxf(xn * K2, -10.0f), 10.0f);
            float r = ex2f(a);
            float z = r + rcpf(r);
            float accq = sCf[14], accs = sCf[30];
            #pragma unroll
            for (int j = 6; j >= 0; --j) {
                accq = fmaf(accq, z, sCf[2 * j]);
                accs = fmaf(accs, z, sCf[16 + 2 * j]);
            }
            float den = (r + 1.0f) * accq;
            float num = (r - 1.0f) * accs;
            sF[i] = num * rcpf(den);
        }
    }
    __syncthreads();
    for (int i = tid; i < TAB_N; i += 256)
        sTabH[i] = __floats2half2_rn(sF[i], sF[i + 1] - sF[i]);
    __syncthreads();

    // ---- stage 3: guard-free persistent loop over FULL tiles ----
    // tile = 256 floats (2 groups of 128); warp covers one tile; lane l:
    // half h = l>>4 -> group, ql = l&15 -> 8 contiguous floats.
    const int lane = tid & 31;
    const int h = lane >> 4;
    const int ql = lane & 15;
    const int W = gridDim.x * 8;                   // total warps
    const int wId = blockIdx.x * 8 + (tid >> 5);
    const int nTfull = n4 >> 6;                    // full 64-quad tiles

    const float pres = sPres;
    const float onemp = 1.0f - pres;

    const int threadByte = (h << 9) + (ql << 5);   // offset within tile
    const long stride = (long)W << 10;             // bytes per warp step

    const char* pIn = reinterpret_cast<const char*>(x) + ((long)wId << 10) + threadByte;
    char*       pOut = reinterpret_cast<char*>(out) + ((long)wId << 10) + threadByte;

    int t = wId;
    float4 a0, a1;
    if (t < nTfull) {
        a0 = *reinterpret_cast<const float4*>(pIn);
        a1 = *reinterpret_cast<const float4*>(pIn + 16);
    }

    #pragma unroll 1
    while (t < nTfull) {
        // depth-1 prefetch
        const char* pNext = pIn + stride;
        float4 b0, b1;
        const bool nv = (t + W) < nTfull;
        if (nv) {
            b0 = *reinterpret_cast<const float4*>(pNext);
            b1 = *reinterpret_cast<const float4*>(pNext + 16);
        }

        // group abs-mean over this 16-lane half (128 elements)
        float ss = (fabsf(a0.x) + fabsf(a0.y)) + (fabsf(a0.z) + fabsf(a0.w))
                 + (fabsf(a1.x) + fabsf(a1.y)) + (fabsf(a1.z) + fabsf(a1.w));
        ss += __shfl_xor_sync(FULL_MASK, ss, 8);
        ss += __shfl_xor_sync(FULL_MASK, ss, 4);
        ss += __shfl_xor_sync(FULL_MASK, ss, 2);
        ss += __shfl_xor_sync(FULL_MASK, ss, 1);
        const float mean_c = fmaxf(ss * (1.0f / 128.0f), 1e-5f);
        const float uScale = TAB_INVH * rcpf(mean_c);
        const float pm = pres * mean_c;

        const float xs[8] = {a0.x, a0.y, a0.z, a0.w, a1.x, a1.y, a1.z, a1.w};

        float res[8];
        #pragma unroll
        for (int e = 0; e < 8; ++e) {
            float u = fmaf(xs[e], uScale, TAB_OFF);
            u = fminf(fmaxf(u, 0.0f), TAB_UMAX);
            int idx = (int)u;
            float frac = u - (float)idx;
            float2 fd = __half22float2(sTabH[idx]);        // LDS.32 + cvt
            float qv = fmaf(frac, fd.y, fd.x);
            res[e] = fmaf(pm, qv, onemp * xs[e]);          // scalar epilogue
        }

        stcs4(reinterpret_cast<float4*>(pOut),
              make_float4(res[0], res[1], res[2], res[3]));
        stcs4(reinterpret_cast<float4*>(pOut + 16),
              make_float4(res[4], res[5], res[6], res[7]));

        pIn = pNext; pOut += stride; t += W;
        a0 = b0; a1 = b1;
    }

    // ---- partial tile (n4 & 63: at most one trailing 32-quad group) ----
    if ((n4 & 63) && t == nTfull) {
        const int qb = t * 64 + h * 32 + ql;       // quad index (old mapping)
        const bool vld = (qb + 16) <= n4;          // group whole-or-absent
        const float4* x4 = reinterpret_cast<const float4*>(x);
        float4 c0 = make_float4(0.f, 0.f, 0.f, 0.f), c1 = c0;
        if (vld) { c0 = x4[qb]; c1 = x4[qb + 16]; }

        float ss = (fabsf(c0.x) + fabsf(c0.y)) + (fabsf(c0.z) + fabsf(c0.w))
                 + (fabsf(c1.x) + fabsf(c1.y)) + (fabsf(c1.z) + fabsf(c1.w));
        ss += __shfl_xor_sync(FULL_MASK, ss, 8);
        ss += __shfl_xor_sync(FULL_MASK, ss, 4);
        ss += __shfl_xor_sync(FULL_MASK, ss, 2);
        ss += __shfl_xor_sync(FULL_MASK, ss, 1);
        const float mean_c = fmaxf(ss * (1.0f / 128.0f), 1e-5f);
        const float uScale = TAB_INVH * rcpf(mean_c);
        const float pm = pres * mean_c;

        const float xs[8] = {c0.x, c0.y, c0.z, c0.w, c1.x, c1.y, c1.z, c1.w};
        float res[8];
        #pragma unroll
        for (int e = 0; e < 8; ++e) {
            float u = fmaf(xs[e], uScale, TAB_OFF);
            u = fminf(fmaxf(u, 0.0f), TAB_UMAX);
            int idx = (int)u;
            float frac = u - (float)idx;
            float2 fd = __half22float2(sTabH[idx]);
            float qv = fmaf(frac, fd.y, fd.x);
            res[e] = fmaf(pm, qv, onemp * xs[e]);
        }
        if (vld) {
            float4* o4 = reinterpret_cast<float4*>(out);
            stcs4(o4 + qb,      make_float4(res[0], res[1], res[2], res[3]));
            stcs4(o4 + qb + 16, make_float4(res[4], res[5], res[6], res[7]));
        }
    }
}

extern "C" void kernel_launch(void* const* d_in, const int* in_sizes, int n_in,
                              void* d_out, int out_size) {
    const float* x  = (const float*)d_in[0];
    const float* cbk = (const float*)d_in[1];
    const float* pr = (const float*)d_in[2];
    const float* tp = (const float*)d_in[3];
    float* out = (float*)d_out;

    const int n4 = out_size / 4;               // float4 quads
    const int numTiles = (n4 + 63) >> 6;
    int blocks = 152 * 5;                      // one resident wave at 5 blocks/SM
    const int maxBlocks = (numTiles + 7) / 8;  // 8 warps/block
    if (blocks > maxBlocks) blocks = maxBlocks;
    if (blocks < 1) blocks = 1;
    ThermoQuantizer_50122268345057_kernel<<<blocks, 256>>>(x, cbk, pr, tp, out, n4);
}

// round 16
// speedup vs baseline: 1.1750x; 1.1750x over previous
#include <cuda_runtime.h>
#include <cuda_bf16.h>
#include <cuda_fp16.h>

// ThermoQuantizer: groupwise abs-mean scale + softmax quantization onto a
// uniform 16-level codebook + lerp.
//
// Core (R13/R14 winners): per-block 2048-entry fp16x2 linear-interp LUT of
// qxn(xn) over [-12,12] built via exact palindromic-Horner; LDS.32 lookups;
// default-policy loads (x lives in L2 across graph replays); .cs stores;
// depth-1 register prefetch; persistent single wave 152x5 blocks.
//
// Round-16: R15's instruction diet (pointer-increment addressing, guard-free
// full-tile loop, scalar epilogue) BUT with R14's interleaved quad mapping
// restored: lane offset (h*32+ql)*16B, second quad at +256B. R15's contiguous
// per-thread mapping doubled per-instruction sector count (L1 53->62%,
// regression); this keeps every LDG/STG at 4 fully-utilized 128B sectors.

typedef unsigned long long ull;
#define FULL_MASK 0xFFFFFFFFu

#define TAB_N    2048
#define TAB_XMIN -12.0f
#define TAB_INVH (2048.0f / 24.0f)
#define TAB_OFF  1024.0f
#define TAB_UMAX 2047.999f

__device__ const float gTcol[56] = {
    0.f,-2.f, 0.f,  2.f, 0.f,-2.f, 0.f,   // j=0
    1.f, 0.f,-3.f,  0.f, 5.f, 0.f,-7.f,   // j=1
    0.f, 1.f, 0.f, -4.f, 0.f, 9.f, 0.f,   // j=2
    0.f, 0.f, 1.f,  0.f,-5.f, 0.f,14.f,   // j=3
    0.f, 0.f, 0.f,  1.f, 0.f,-6.f, 0.f,   // j=4
    0.f, 0.f, 0.f,  0.f, 1.f, 0.f,-7.f,   // j=5
    0.f, 0.f, 0.f,  0.f, 0.f, 1.f, 0.f,   // j=6
    0.f, 0.f, 0.f,  0.f, 0.f, 0.f, 1.f};  // j=7

__device__ __forceinline__ ull pk2(float lo, float hi) {
    ull r; asm("mov.b64 %0, {%1, %2};" : "=l"(r) : "f"(lo), "f"(hi)); return r;
}
__device__ __forceinline__ float ex2f(float a) {
    float r; asm("ex2.approx.ftz.f32 %0, %1;" : "=f"(r) : "f"(a)); return r;
}
__device__ __forceinline__ float rcpf(float a) {
    float r; asm("rcp.approx.ftz.f32 %0, %1;" : "=f"(r) : "f"(a)); return r;
}
__device__ __forceinline__ void stcs4(float4* p, float4 v) {
    asm volatile("st.global.cs.v4.f32 [%0], {%1,%2,%3,%4};"
                 :: "l"(p), "f"(v.x), "f"(v.y), "f"(v.z), "f"(v.w) : "memory");
}

__global__ __launch_bounds__(256, 5) void ThermoQuantizer_50122268345057_kernel(
    const float* __restrict__ x,
    const float* __restrict__ cb,
    const float* __restrict__ pp,
    const float* __restrict__ pt,
    float* __restrict__ out,
    int n4)
{
    __shared__ __half2 sTabH[TAB_N];     // packed fp16 (f_i, f_{i+1}-f_i)
    __shared__ float sF[TAB_N + 1];      // node values (build scratch, fp32)
    __shared__ ull   sC[16];             // (q_j,q_j) j=0..7 then (s_j,s_j)
    __shared__ float sK2, sPres;

    const int tid = threadIdx.x;

    // ---- stage 1: Q,S coefficient derivation (warp 0, lane-parallel) ----
    if (tid < 32) {
        const int lane0 = tid;
        const int k = lane0 & 15;
        const float invT = 1.0f / (pt[0] + 1e-6f);
        const float c = cb[k];
        const float g = __expf(-c * c * invT);
        const float Hk = g * c;

        float sg = (k & 1) ? -g : g;     // p: alternating prefix sum
        float sh = Hk;                   // m: plain prefix sum (negated)
        #pragma unroll
        for (int o = 1; o <= 8; o <<= 1) {
            float tg = __shfl_up_sync(FULL_MASK, sg, o);
            float th = __shfl_up_sync(FULL_MASK, sh, o);
            if (lane0 >= o) { sg += tg; sh += th; }
        }
        const float pv = (k & 1) ? -sg : sg;
        const float mv = -sh;

        float pb[8], mb[8];
        #pragma unroll
        for (int t = 0; t < 8; ++t) {
            pb[t] = __shfl_sync(FULL_MASK, pv, 7 + t);
            mb[t] = __shfl_sync(FULL_MASK, mv, 7 + t);
        }
        if (lane0 < 8) {
            float q = (lane0 == 0) ? pb[0] : 0.f;
            float s = (lane0 == 0) ? mb[0] : 0.f;
            const float* Tc = &gTcol[lane0 * 7];
            #pragma unroll
            for (int t = 1; t <= 7; ++t) {
                float tc = Tc[t - 1];
                q = fmaf(pb[t], tc, q);
                s = fmaf(mb[t], tc, s);
            }
            sC[lane0]     = pk2(q, q);
            sC[lane0 + 8] = pk2(s, s);
        }
        if (lane0 == 0) {
            sK2 = 2.0f * (cb[1] - cb[0]) * invT * 1.4426950408889634f;
            sPres = pp[0];
        }
    }
    __syncthreads();

    // ---- stage 2: build qxn table (all 256 threads), pack to fp16x2 ----
    {
        const float* sCf = reinterpret_cast<const float*>(sC);
        const float K2 = sK2;
        for (int i = tid; i <= TAB_N; i += 256) {
            float xn = TAB_XMIN + (float)i * (1.0f / TAB_INVH);
            float a = fminf(fmaxf(xn * K2, -10.0f), 10.0f);
            float r = ex2f(a);
            float z = r + rcpf(r);
            float accq = sCf[14], accs = sCf[30];
            #pragma unroll
            for (int j = 6; j >= 0; --j) {
                accq = fmaf(accq, z, sCf[2 * j]);
                accs = fmaf(accs, z, sCf[16 + 2 * j]);
            }
            float den = (r + 1.0f) * accq;
            float num = (r - 1.0f) * accs;
            sF[i] = num * rcpf(den);
        }
    }
    __syncthreads();
    for (int i = tid; i < TAB_N; i += 256)
        sTabH[i] = __floats2half2_rn(sF[i], sF[i + 1] - sF[i]);
    __syncthreads();

    // ---- stage 3: guard-free persistent loop over FULL tiles ----
    // tile = 64 quads (2 groups of 32 quads); warp covers one tile.
    // Interleaved mapping: lane quad = h*32 + ql, second quad at +16 (=+256B)
    // -> every LDG/STG is two contiguous 256B runs = 4 full 128B sectors.
    const int lane = tid & 31;
    const int h = lane >> 4;
    const int ql = lane & 15;
    const int W = gridDim.x * 8;                   // total warps
    const int wId = blockIdx.x * 8 + (tid >> 5);
    const int nTfull = n4 >> 6;                    // full 64-quad tiles

    const float pres = sPres;
    const float onemp = 1.0f - pres;

    const int threadByte = (h << 9) + (ql << 4);   // (h*32+ql)*16 bytes
    const long stride = (long)W << 10;             // 1024B per warp step

    const char* pIn  = reinterpret_cast<const char*>(x) + ((long)wId << 10) + threadByte;
    char*       pOut = reinterpret_cast<char*>(out) + ((long)wId << 10) + threadByte;

    int t = wId;
    float4 a0, a1;
    if (t < nTfull) {
        a0 = *reinterpret_cast<const float4*>(pIn);
        a1 = *reinterpret_cast<const float4*>(pIn + 256);
    }

    #pragma unroll 1
    while (t < nTfull) {
        // depth-1 prefetch
        const char* pNext = pIn + stride;
        float4 b0, b1;
        const bool nv = (t + W) < nTfull;
        if (nv) {
            b0 = *reinterpret_cast<const float4*>(pNext);
            b1 = *reinterpret_cast<const float4*>(pNext + 256);
        }

        // group abs-mean over this 16-lane half (128 elements)
        float ss = (fabsf(a0.x) + fabsf(a0.y)) + (fabsf(a0.z) + fabsf(a0.w))
                 + (fabsf(a1.x) + fabsf(a1.y)) + (fabsf(a1.z) + fabsf(a1.w));
        ss += __shfl_xor_sync(FULL_MASK, ss, 8);
        ss += __shfl_xor_sync(FULL_MASK, ss, 4);
        ss += __shfl_xor_sync(FULL_MASK, ss, 2);
        ss += __shfl_xor_sync(FULL_MASK, ss, 1);
        const float mean_c = fmaxf(ss * (1.0f / 128.0f), 1e-5f);
        const float uScale = TAB_INVH * rcpf(mean_c);
        const float pm = pres * mean_c;

        const float xs[8] = {a0.x, a0.y, a0.z, a0.w, a1.x, a1.y, a1.z, a1.w};

        float res[8];
        #pragma unroll
        for (int e = 0; e < 8; ++e) {
            float u = fmaf(xs[e], uScale, TAB_OFF);
            u = fminf(fmaxf(u, 0.0f), TAB_UMAX);
            int idx = (int)u;
            float frac = u - (float)idx;
            float2 fd = __half22float2(sTabH[idx]);        // LDS.32 + cvt
            float qv = fmaf(frac, fd.y, fd.x);
            res[e] = fmaf(pm, qv, onemp * xs[e]);          // scalar epilogue
        }

        stcs4(reinterpret_cast<float4*>(pOut),
              make_float4(res[0], res[1], res[2], res[3]));
        stcs4(reinterpret_cast<float4*>(pOut + 256),
              make_float4(res[4], res[5], res[6], res[7]));

        pIn = pNext; pOut += stride; t += W;
        a0 = b0; a1 = b1;
    }

    // ---- partial tile (n4 & 63: at most one trailing 32-quad group) ----
    if ((n4 & 63) && t == nTfull) {
        const int qb = t * 64 + h * 32 + ql;       // quad index
        const bool vld = (qb + 16) <= n4;          // group whole-or-absent
        const float4* x4 = reinterpret_cast<const float4*>(x);
        float4 c0 = make_float4(0.f, 0.f, 0.f, 0.f), c1 = c0;
        if (vld) { c0 = x4[qb]; c1 = x4[qb + 16]; }

        float ss = (fabsf(c0.x) + fabsf(c0.y)) + (fabsf(c0.z) + fabsf(c0.w))
                 + (fabsf(c1.x) + fabsf(c1.y)) + (fabsf(c1.z) + fabsf(c1.w));
        ss += __shfl_xor_sync(FULL_MASK, ss, 8);
        ss += __shfl_xor_sync(FULL_MASK, ss, 4);
        ss += __shfl_xor_sync(FULL_MASK, ss, 2);
        ss += __shfl_xor_sync(FULL_MASK, ss, 1);
        const float mean_c = fmaxf(ss * (1.0f / 128.0f), 1e-5f);
        const float uScale = TAB_INVH * rcpf(mean_c);
        const float pm = pres * mean_c;

        const float xs[8] = {c0.x, c0.y, c0.z, c0.w, c1.x, c1.y, c1.z, c1.w};
        float res[8];
        #pragma unroll
        for (int e = 0; e < 8; ++e) {
            float u = fmaf(xs[e], uScale, TAB_OFF);
            u = fminf(fmaxf(u, 0.0f), TAB_UMAX);
            int idx = (int)u;
            float frac = u - (float)idx;
            float2 fd = __half22float2(sTabH[idx]);
            float qv = fmaf(frac, fd.y, fd.x);
            res[e] = fmaf(pm, qv, onemp * xs[e]);
        }
        if (vld) {
            float4* o4 = reinterpret_cast<float4*>(out);
            stcs4(o4 + qb,      make_float4(res[0], res[1], res[2], res[3]));
            stcs4(o4 + qb + 16, make_float4(res[4], res[5], res[6], res[7]));
        }
    }
}

extern "C" void kernel_launch(void* const* d_in, const int* in_sizes, int n_in,
                              void* d_out, int out_size) {
    const float* x  = (const float*)d_in[0];
    const float* cbk = (const float*)d_in[1];
    const float* pr = (const float*)d_in[2];
    const float* tp = (const float*)d_in[3];
    float* out = (float*)d_out;

    const int n4 = out_size / 4;               // float4 quads
    const int numTiles = (n4 + 63) >> 6;
    int blocks = 152 * 5;                      // one resident wave at 5 blocks/SM
    const int maxBlocks = (numTiles + 7) / 8;  // 8 warps/block
    if (blocks > maxBlocks) blocks = maxBlocks;
    if (blocks < 1) blocks = 1;
    ThermoQuantizer_50122268345057_kernel<<<blocks, 256>>>(x, cbk, pr, tp, out, n4);
}